// round 12
// baseline (speedup 1.0000x reference)
#include <cuda_runtime.h>
#include <cstdint>

#define Bn   16
#define Tn   512
#define INn  128
#define Hn   256
#define Dn   8
#define EPSf 1e-5f

#define CL        8            // CTAs per cluster (8-way k/row split)
#define SCAN_CTAS 128          // 16 batches x 8 CTAs
#define GRID_SCAN 256          // 128 scan CTAs + 128 zero-fill CTAs

// ---------------- scratch (static device arrays; no allocation) ----------------
__device__ float g_xproj[Bn * Tn * Hn];   // 8 MB
__device__ float g_enc  [Bn * Tn * Hn];   // 8 MB
__device__ float g_bd   [Bn * Tn * 2 * Dn]; // 512 KB

// ---------------- helpers ----------------
__device__ __forceinline__ uint32_t smem_u32(const void* p) {
    uint32_t a;
    asm("{ .reg .u64 t; cvta.to.shared.u64 t, %1; cvt.u32.u64 %0, t; }"
        : "=r"(a) : "l"(p));
    return a;
}

__device__ __forceinline__ uint32_t cluster_rank() {
    uint32_t r;
    asm("mov.u32 %0, %%cluster_ctarank;" : "=r"(r));
    return r;
}

__device__ __forceinline__ uint32_t mapa_u32(uint32_t local_addr, uint32_t rank) {
    uint32_t r;
    asm("mapa.shared::cluster.u32 %0, %1, %2;" : "=r"(r) : "r"(local_addr), "r"(rank));
    return r;
}

__device__ __forceinline__ unsigned long long pack2(float x, float y) {
    unsigned long long r;
    asm("mov.b64 %0, {%1, %2};" : "=l"(r) : "f"(x), "f"(y));
    return r;
}
__device__ __forceinline__ void unpack2(unsigned long long v, float& x, float& y) {
    asm("mov.b64 {%0, %1}, %2;" : "=f"(x), "=f"(y) : "l"(v));
}
// packed fp32x2 FMA (Blackwell FFMA2): 2 fp32 MACs per instruction
__device__ __forceinline__ void ffma2(unsigned long long& d,
                                      unsigned long long a,
                                      unsigned long long b) {
    asm("fma.rn.f32x2 %0, %1, %2, %3;" : "=l"(d) : "l"(a), "l"(b), "l"(d));
}

__device__ __forceinline__ float tanh_approx(float x) {
    float r;
    asm("tanh.approx.f32 %0, %1;" : "=f"(r) : "f"(x));
    return r;
}

__device__ __forceinline__ void mbar_init(uint32_t addr, uint32_t count) {
    asm volatile("mbarrier.init.shared.b64 [%0], %1;" :: "r"(addr), "r"(count) : "memory");
}

__device__ __forceinline__ void mbar_arrive_expect_tx(uint32_t addr, uint32_t bytes) {
    asm volatile("mbarrier.arrive.expect_tx.shared.b64 _, [%0], %1;"
                 :: "r"(addr), "r"(bytes) : "memory");
}

__device__ __forceinline__ void mbar_wait(uint32_t addr, int phase) {
    asm volatile(
        "{\n\t"
        ".reg .pred P1;\n\t"
        "LAB_%=:\n\t"
        "mbarrier.try_wait.parity.acquire.cta.shared::cta.b64 P1, [%0], %1, 0x989680;\n\t"
        "@P1 bra DONE_%=;\n\t"
        "bra LAB_%=;\n\t"
        "DONE_%=:\n\t"
        "}"
        :: "r"(addr), "r"(phase) : "memory");
}

// async remote smem store (b32) with tx-completion on the remote mbarrier
__device__ __forceinline__ void st_async_f32(uint32_t raddr, float v, uint32_t rmbar) {
    asm volatile(
        "st.async.shared::cluster.mbarrier::complete_tx::bytes.b32 [%0], %1, [%2];"
        :: "r"(raddr), "r"(__float_as_uint(v)), "r"(rmbar) : "memory");
}

// ---------------- kernel 1: x_proj = y @ W_ih^T + b_ih ----------------
__global__ void k_xproj(const float* __restrict__ y,
                        const float* __restrict__ W_ih,
                        const float* __restrict__ b_ih) {
    const int h  = threadIdx.x;       // 0..255
    const int b  = blockIdx.y;
    const int t0 = blockIdx.x * 4;

    const float4* Wr = reinterpret_cast<const float4*>(W_ih + h * INn);
    const float4* Y  = reinterpret_cast<const float4*>(y + ((size_t)b * Tn + t0) * INn);

    float a0 = 0.f, a1 = 0.f, a2 = 0.f, a3 = 0.f;
#pragma unroll 4
    for (int k = 0; k < 32; k++) {
        float4 wv = __ldg(Wr + k);
        float4 y0 = __ldg(Y + k);
        float4 y1 = __ldg(Y + 32 + k);
        float4 y2 = __ldg(Y + 64 + k);
        float4 y3 = __ldg(Y + 96 + k);
        a0 += wv.x * y0.x + wv.y * y0.y + wv.z * y0.z + wv.w * y0.w;
        a1 += wv.x * y1.x + wv.y * y1.y + wv.z * y1.z + wv.w * y1.w;
        a2 += wv.x * y2.x + wv.y * y2.y + wv.z * y2.z + wv.w * y2.w;
        a3 += wv.x * y3.x + wv.y * y3.y + wv.z * y3.z + wv.w * y3.w;
    }
    const float bias = __ldg(b_ih + h);
    size_t base = ((size_t)b * Tn + t0) * Hn + h;
    g_xproj[base]          = a0 + bias;
    g_xproj[base + Hn]     = a1 + bias;
    g_xproj[base + 2 * Hn] = a2 + bias;
    g_xproj[base + 3 * Hn] = a3 + bias;
}

// ---------------- kernel 2: RNN scan (8-way cluster split) + prec zero-fill ----------------
// Grid 256, clusters of 8. CTAs [0,128): scan (16 clusters, one per batch).
// CTAs [128,256): zero-fill prec on otherwise-idle SMs.
// Scan: CTA rank r holds W_hh[:, r*32:+32) (thread tid = output row, 16 f32x2
// regs) and OWNS output rows [r*32,+32). Matching row/k split: each CTA only
// needs the h-slice it finalizes; only partials cross CTAs.
// Per step: 32-wide dot (16 FFMA2 — shippers' messages leave very early),
// non-own threads ship partial to the row's owner; owner's 32 finalizer
// threads wait on mbar (896 B = 7 sources x 32 rows), 8-way sum, tanh.
__global__ void __cluster_dims__(CL, 1, 1) __launch_bounds__(256, 1)
k_scan(const float* __restrict__ W_hh, const float* __restrict__ b_hh,
       float* __restrict__ prec) {
    // ---- zero-fill CTAs ----
    if (blockIdx.x >= SCAN_CTAS) {
        const long long total = (long long)Bn * Dn * Tn * Tn / 4;   // float4 count
        const int nz = GRID_SCAN - SCAN_CTAS;
        long long i = (long long)(blockIdx.x - SCAN_CTAS) * blockDim.x + threadIdx.x;
        const long long stride = (long long)nz * blockDim.x;
        const float4 z = make_float4(0.f, 0.f, 0.f, 0.f);
        for (; i < total; i += stride)
            __stcs(reinterpret_cast<float4*>(prec) + i, z);
        return;
    }

    __shared__ __align__(16) float hbuf[2][32];      // this CTA's OWNED h slice
    __shared__ __align__(16) float ps_in[2][CL][32]; // incoming partials by source rank
    __shared__ __align__(8) unsigned long long mbar[2];

    const int tid = threadIdx.x;                 // = global output row
    const unsigned rank = cluster_rank();        // 0..7
    const int batch = blockIdx.x >> 3;
    const unsigned owner = (unsigned)tid >> 5;   // owner CTA of this row
    const bool own = (owner == rank);
    const int lrow = tid & 31;

    // register-resident weights: W_hh[tid, rank*32 .. +32)  (16 f32x2)
    unsigned long long w[16];
    {
        const float2* wr = reinterpret_cast<const float2*>(W_hh + (size_t)tid * Hn + (rank << 5));
#pragma unroll
        for (int i = 0; i < 16; i++) {
            float2 v = __ldg(wr + i);
            w[i] = pack2(v.x, v.y);
        }
    }
    const float bias = own ? __ldg(b_hh + tid) : 0.f;
    const float* xcol = g_xproj + (size_t)batch * Tn * Hn + tid;

    if (tid == 0) { mbar_init(smem_u32(&mbar[0]), 1); mbar_init(smem_u32(&mbar[1]), 1); }
    if (tid < 32) { hbuf[0][tid] = 0.f; }                       // h(-1) = 0
    for (int i = tid; i < 2 * CL * 32; i += 256)                // zero ps_in (own slot stays 0)
        reinterpret_cast<float*>(ps_in)[i] = 0.f;
    __syncthreads();
    asm volatile("barrier.cluster.arrive.aligned;" ::: "memory");
    asm volatile("barrier.cluster.wait.aligned;" ::: "memory");

    // remote targets for shippers: slot [buf][my_rank][lrow] in owner CTA
    uint32_t r_ps[2] = {0, 0}, r_mbar[2] = {0, 0};
    if (!own) {
        r_ps[0]   = mapa_u32(smem_u32(&ps_in[0][rank][lrow]), owner);
        r_ps[1]   = mapa_u32(smem_u32(&ps_in[1][rank][lrow]), owner);
        r_mbar[0] = mapa_u32(smem_u32(&mbar[0]), owner);
        r_mbar[1] = mapa_u32(smem_u32(&mbar[1]), owner);
    }
    const uint32_t l_mbar[2] = { smem_u32(&mbar[0]), smem_u32(&mbar[1]) };

    int ph[2] = {0, 0};
    float xv = own ? __ldg(xcol) : 0.f;   // x for t=0

    for (int t = 0; t < Tn; ++t) {
        const int buf = t & 1;
        const int nb  = buf ^ 1;

        // prefetch next x (finalizer threads), latency hidden behind FMA
        float xnext = 0.f;
        if (own && (t + 1) < Tn) xnext = __ldg(xcol + (size_t)(t + 1) * Hn);

        // expect 7 sources x 32 rows x 4 B
        if (tid == 0) mbar_arrive_expect_tx(l_mbar[buf], 896);

        // 32-wide dot over owned h slice (16 FFMA2)
        const ulonglong2* hp = reinterpret_cast<const ulonglong2*>(hbuf[buf]);
        unsigned long long acc0 = 0ull, acc1 = 0ull;
#pragma unroll
        for (int i = 0; i < 8; i++) {
            ulonglong2 hv = hp[i];
            ffma2(acc0, w[2 * i],     hv.x);
            ffma2(acc1, w[2 * i + 1], hv.y);
        }
        float a0, a1, c0, c1;
        unpack2(acc0, a0, a1);
        unpack2(acc1, c0, c1);
        const float part = (a0 + c0) + (a1 + c1);

        if (!own) {
            // ship partial to the row's owner; drains in background
            st_async_f32(r_ps[buf], part, r_mbar[buf]);
        } else {
            mbar_wait(l_mbar[buf], ph[buf]);
            ph[buf] ^= 1;
            // own slot is permanently 0 -> unconditional 8-way sum
            const float* p = &ps_in[buf][0][lrow];
            float s = part + xv + bias
                    + (p[0] + p[32]) + (p[64] + p[96])
                    + (p[128] + p[160]) + (p[192] + p[224]);
            float hn = tanh_approx(s);
            xv = xnext;
            hbuf[nb][lrow] = hn;                               // STS first
            g_enc[((size_t)batch * Tn + t) * Hn + tid] = hn;   // then global
        }
        __syncthreads();
    }

    // keep smem/barriers alive until peers' in-flight st.asyncs complete
    asm volatile("barrier.cluster.arrive.aligned;" ::: "memory");
    asm volatile("barrier.cluster.wait.aligned;" ::: "memory");
}

// ---------------- kernel 3: mean + bd heads ----------------
__global__ void k_meanbd(const float* __restrict__ W_mean, const float* __restrict__ b_mean,
                         const float* __restrict__ W_bd,   const float* __restrict__ b_bd,
                         float* __restrict__ out_mean) {
    const int local = threadIdx.x;            // 0..191
    const int o  = local % 24;
    const int r  = local / 24;
    const int bt = blockIdx.x * 8 + r;        // 0..8191

    const float4* e4 = reinterpret_cast<const float4*>(g_enc + (size_t)bt * Hn);
    const float4* w4;
    float bias;
    if (o < Dn) { w4 = reinterpret_cast<const float4*>(W_mean + o * Hn);        bias = __ldg(b_mean + o); }
    else        { w4 = reinterpret_cast<const float4*>(W_bd + (o - Dn) * Hn);   bias = __ldg(b_bd + (o - Dn)); }

    float acc = 0.f;
#pragma unroll 8
    for (int k = 0; k < 64; k++) {
        float4 ev = __ldg(e4 + k);
        float4 wv = __ldg(w4 + k);
        acc += ev.x * wv.x + ev.y * wv.y + ev.z * wv.z + ev.w * wv.w;
    }
    acc += bias;
    if (o < Dn) out_mean[(size_t)bt * Dn + o] = acc;
    else        g_bd[(size_t)bt * (2 * Dn) + (o - Dn)] = acc;
}

// ---------------- kernel 4: tridiagonal writes only (zeros done in k_scan) ----------------
__global__ void __launch_bounds__(256) k_prec_diag(float* __restrict__ prec) {
    const int idx = blockIdx.x * 256 + threadIdx.x;   // 0 .. 65535 = (b*8+d)*512 + i
    const int i   = idx & 511;
    const int bd_ = idx >> 9;
    const int d   = bd_ & 7;
    const int b   = bd_ >> 3;

    const size_t row = ((size_t)b * Tn + i) * 16;
    float diag_i = g_bd[row + d];
    float off_i  = g_bd[row + 8 + d];
    float off_p  = 0.f;
    if (i > 0) off_p = g_bd[row - 16 + 8 + d];

    float mainv  = diag_i * diag_i + off_p * off_p + EPSf;
    float supd_r = diag_i * off_i;   // supd[i] (columns i/i+1)

    float* base = prec + ((size_t)bd_ * Tn + i) * Tn + i;   // [b,d,i,i]
    base[0] = mainv;
    if (i < Tn - 1) {
        base[1]  = supd_r;    // [i, i+1]
        base[Tn] = supd_r;    // [i+1, i]
    }
}

// ---------------- launch ----------------
extern "C" void kernel_launch(void* const* d_in, const int* in_sizes, int n_in,
                              void* d_out, int out_size) {
    const float* y      = (const float*)d_in[0];
    const float* W_ih   = (const float*)d_in[1];
    const float* W_hh   = (const float*)d_in[2];
    const float* b_ih   = (const float*)d_in[3];
    const float* b_hh   = (const float*)d_in[4];
    const float* W_mean = (const float*)d_in[5];
    const float* b_mean = (const float*)d_in[6];
    const float* W_bd   = (const float*)d_in[7];
    const float* b_bd   = (const float*)d_in[8];
    float* out = (float*)d_out;
    float* prec = out + Bn * Tn * Dn;

    k_xproj<<<dim3(Tn / 4, Bn), 256>>>(y, W_ih, b_ih);
    k_scan<<<GRID_SCAN, 256>>>(W_hh, b_hh, prec);          // scan + prec zero-fill
    k_meanbd<<<(Bn * Tn) / 8, 192>>>(W_mean, b_mean, W_bd, b_bd, out);
    k_prec_diag<<<(Bn * Dn * Tn) / 256, 256>>>(prec);
}

// round 13
// speedup vs baseline: 1.1329x; 1.1329x over previous
#include <cuda_runtime.h>
#include <cstdint>

#define Bn   16
#define Tn   512
#define INn  128
#define Hn   256
#define Dn   8
#define EPSf 1e-5f

#define CL        4            // CTAs per cluster (4-way k/row split) — measured optimum
#define SCAN_CTAS 64           // 16 batches x 4 CTAs
#define GRID_SCAN 256          // 64 scan CTAs + 192 zero-fill CTAs

// ---------------- scratch (static device arrays; no allocation) ----------------
__device__ float g_xproj[Bn * Tn * Hn];          // 8 MB
__device__ float g_bd   [Bn * Tn * 2 * Dn];      // 512 KB
__device__ float g_hp   [Bn * Tn * CL * 24];     // 3 MB: per-rank head partials

// ---------------- helpers ----------------
__device__ __forceinline__ uint32_t smem_u32(const void* p) {
    uint32_t a;
    asm("{ .reg .u64 t; cvta.to.shared.u64 t, %1; cvt.u32.u64 %0, t; }"
        : "=r"(a) : "l"(p));
    return a;
}

__device__ __forceinline__ uint32_t cluster_rank() {
    uint32_t r;
    asm("mov.u32 %0, %%cluster_ctarank;" : "=r"(r));
    return r;
}

__device__ __forceinline__ uint32_t mapa_u32(uint32_t local_addr, uint32_t rank) {
    uint32_t r;
    asm("mapa.shared::cluster.u32 %0, %1, %2;" : "=r"(r) : "r"(local_addr), "r"(rank));
    return r;
}

__device__ __forceinline__ unsigned long long pack2(float x, float y) {
    unsigned long long r;
    asm("mov.b64 %0, {%1, %2};" : "=l"(r) : "f"(x), "f"(y));
    return r;
}
__device__ __forceinline__ void unpack2(unsigned long long v, float& x, float& y) {
    asm("mov.b64 {%0, %1}, %2;" : "=f"(x), "=f"(y) : "l"(v));
}
// packed fp32x2 FMA (Blackwell FFMA2): 2 fp32 MACs per instruction
__device__ __forceinline__ void ffma2(unsigned long long& d,
                                      unsigned long long a,
                                      unsigned long long b) {
    asm("fma.rn.f32x2 %0, %1, %2, %3;" : "=l"(d) : "l"(a), "l"(b), "l"(d));
}

__device__ __forceinline__ float tanh_approx(float x) {
    float r;
    asm("tanh.approx.f32 %0, %1;" : "=f"(r) : "f"(x));
    return r;
}

__device__ __forceinline__ void mbar_init(uint32_t addr, uint32_t count) {
    asm volatile("mbarrier.init.shared.b64 [%0], %1;" :: "r"(addr), "r"(count) : "memory");
}

__device__ __forceinline__ void mbar_arrive_expect_tx(uint32_t addr, uint32_t bytes) {
    asm volatile("mbarrier.arrive.expect_tx.shared.b64 _, [%0], %1;"
                 :: "r"(addr), "r"(bytes) : "memory");
}

__device__ __forceinline__ void mbar_wait(uint32_t addr, int phase) {
    asm volatile(
        "{\n\t"
        ".reg .pred P1;\n\t"
        "LAB_%=:\n\t"
        "mbarrier.try_wait.parity.acquire.cta.shared::cta.b64 P1, [%0], %1, 0x989680;\n\t"
        "@P1 bra DONE_%=;\n\t"
        "bra LAB_%=;\n\t"
        "DONE_%=:\n\t"
        "}"
        :: "r"(addr), "r"(phase) : "memory");
}

// async remote smem store (b32) with tx-completion on the remote mbarrier
__device__ __forceinline__ void st_async_f32(uint32_t raddr, float v, uint32_t rmbar) {
    asm volatile(
        "st.async.shared::cluster.mbarrier::complete_tx::bytes.b32 [%0], %1, [%2];"
        :: "r"(raddr), "r"(__float_as_uint(v)), "r"(rmbar) : "memory");
}

// ---------------- kernel 1: x_proj = y @ W_ih^T + b_ih ----------------
__global__ void k_xproj(const float* __restrict__ y,
                        const float* __restrict__ W_ih,
                        const float* __restrict__ b_ih) {
    const int h  = threadIdx.x;       // 0..255
    const int b  = blockIdx.y;
    const int t0 = blockIdx.x * 4;

    const float4* Wr = reinterpret_cast<const float4*>(W_ih + h * INn);
    const float4* Y  = reinterpret_cast<const float4*>(y + ((size_t)b * Tn + t0) * INn);

    float a0 = 0.f, a1 = 0.f, a2 = 0.f, a3 = 0.f;
#pragma unroll 4
    for (int k = 0; k < 32; k++) {
        float4 wv = __ldg(Wr + k);
        float4 y0 = __ldg(Y + k);
        float4 y1 = __ldg(Y + 32 + k);
        float4 y2 = __ldg(Y + 64 + k);
        float4 y3 = __ldg(Y + 96 + k);
        a0 += wv.x * y0.x + wv.y * y0.y + wv.z * y0.z + wv.w * y0.w;
        a1 += wv.x * y1.x + wv.y * y1.y + wv.z * y1.z + wv.w * y1.w;
        a2 += wv.x * y2.x + wv.y * y2.y + wv.z * y2.z + wv.w * y2.w;
        a3 += wv.x * y3.x + wv.y * y3.y + wv.z * y3.z + wv.w * y3.w;
    }
    const float bias = __ldg(b_ih + h);
    size_t base = ((size_t)b * Tn + t0) * Hn + h;
    g_xproj[base]          = a0 + bias;
    g_xproj[base + Hn]     = a1 + bias;
    g_xproj[base + 2 * Hn] = a2 + bias;
    g_xproj[base + 3 * Hn] = a3 + bias;
}

// ---------------- kernel 2: RNN scan (CL=4) + in-scan head partials + prec zero-fill ----------------
// Grid 256, clusters of 4. CTAs [0,64): scan. CTAs [64,256): zero-fill prec.
// Scan: CTA rank r owns rows [r*64,+64) and W_hh[:, r*64:+64) in registers.
// NEW: 96 of the 192 shipper threads (idle during the ~800-cyc mbar wait)
// compute mean/bd head partials for h(t-1) over the local h slice and write
// 24 floats/CTA/step to g_hp. Replaces the k_meanbd kernel AND removes g_enc.
__global__ void __cluster_dims__(CL, 1, 1) __launch_bounds__(256, 1)
k_scan(const float* __restrict__ W_hh, const float* __restrict__ b_hh,
       const float* __restrict__ W_mean, const float* __restrict__ W_bd,
       float* __restrict__ prec) {
    // ---- zero-fill CTAs ----
    if (blockIdx.x >= SCAN_CTAS) {
        const long long total = (long long)Bn * Dn * Tn * Tn / 4;   // float4 count
        const int nz = GRID_SCAN - SCAN_CTAS;
        long long i = (long long)(blockIdx.x - SCAN_CTAS) * blockDim.x + threadIdx.x;
        const long long stride = (long long)nz * blockDim.x;
        const float4 z = make_float4(0.f, 0.f, 0.f, 0.f);
        for (; i < total; i += stride)
            __stcs(reinterpret_cast<float4*>(prec) + i, z);
        return;
    }

    __shared__ __align__(16) float hbuf[2][64];      // this CTA's OWNED h slice
    __shared__ __align__(16) float ps_in[2][CL][64]; // incoming partials by source rank
    __shared__ __align__(8) unsigned long long mbar[2];

    const int tid = threadIdx.x;                 // = global output row
    const unsigned rank = cluster_rank();        // 0..3
    const int batch = blockIdx.x >> 2;
    const unsigned owner = (unsigned)tid >> 6;   // owner CTA of this row
    const bool own = (owner == rank);
    const int lrow = tid & 63;

    // register-resident weights: W_hh[tid, rank*64 .. +64)  (32 f32x2)
    unsigned long long w[32];
    {
        const float2* wr = reinterpret_cast<const float2*>(W_hh + (size_t)tid * Hn + (rank << 6));
#pragma unroll
        for (int i = 0; i < 32; i++) {
            float2 v = __ldg(wr + i);
            w[i] = pack2(v.x, v.y);
        }
    }
    const float bias = own ? __ldg(b_hh + tid) : 0.f;
    const float* xcol = g_xproj + (size_t)batch * Tn * Hn + tid;

    // ---- head-partial worker setup (96 shipper threads per CTA) ----
    // shipper index sid: 0..191 over shipper threads (64-aligned chunks -> whole warps)
    const int sid = (tid >= (int)((rank << 6) + 64)) ? tid - 64 : tid;
    const bool worker = (!own) && (sid < 96);    // warp-aligned cutoff
    const int ho = sid >> 2;                     // head output 0..23 (8 mean + 16 bd)
    const int hq = sid & 3;                      // 16-wide k sub-quarter
    unsigned long long wh[8];
    if (worker) {
        const float* whrow = (ho < Dn ? W_mean + ho * Hn : W_bd + (ho - Dn) * Hn)
                             + (rank << 6) + (hq << 4);
        const float2* wh2 = reinterpret_cast<const float2*>(whrow);
#pragma unroll
        for (int i = 0; i < 8; i++) {
            float2 v = __ldg(wh2 + i);
            wh[i] = pack2(v.x, v.y);
        }
    }
    float* hp_base = g_hp + ((size_t)batch * Tn * CL + rank) * 24 + ho;

    if (tid == 0) { mbar_init(smem_u32(&mbar[0]), 1); mbar_init(smem_u32(&mbar[1]), 1); }
    if (tid < 64) { hbuf[0][tid] = 0.f; }                       // h(-1) = 0
    for (int i = tid; i < 2 * CL * 64; i += 256)                // zero ps_in (own slot stays 0)
        reinterpret_cast<float*>(ps_in)[i] = 0.f;
    __syncthreads();
    asm volatile("barrier.cluster.arrive.aligned;" ::: "memory");
    asm volatile("barrier.cluster.wait.aligned;" ::: "memory");

    // remote targets for shippers: slot [buf][my_rank][lrow] in owner CTA
    uint32_t r_ps[2] = {0, 0}, r_mbar[2] = {0, 0};
    if (!own) {
        r_ps[0]   = mapa_u32(smem_u32(&ps_in[0][rank][lrow]), owner);
        r_ps[1]   = mapa_u32(smem_u32(&ps_in[1][rank][lrow]), owner);
        r_mbar[0] = mapa_u32(smem_u32(&mbar[0]), owner);
        r_mbar[1] = mapa_u32(smem_u32(&mbar[1]), owner);
    }
    const uint32_t l_mbar[2] = { smem_u32(&mbar[0]), smem_u32(&mbar[1]) };

    int ph[2] = {0, 0};
    float xv = own ? __ldg(xcol) : 0.f;   // x for t=0

    for (int t = 0; t < Tn; ++t) {
        const int buf = t & 1;
        const int nb  = buf ^ 1;

        // prefetch next x (finalizer threads), latency hidden behind FMA
        float xnext = 0.f;
        if (own && (t + 1) < Tn) xnext = __ldg(xcol + (size_t)(t + 1) * Hn);

        // expect 3 sources x 64 rows x 4 B
        if (tid == 0) mbar_arrive_expect_tx(l_mbar[buf], 768);

        // 64-wide dot over owned h slice (32 FFMA2)
        const ulonglong2* hp = reinterpret_cast<const ulonglong2*>(hbuf[buf]);
        unsigned long long acc0 = 0ull, acc1 = 0ull;
#pragma unroll
        for (int i = 0; i < 16; i++) {
            ulonglong2 hv = hp[i];
            ffma2(acc0, w[2 * i],     hv.x);
            ffma2(acc1, w[2 * i + 1], hv.y);
        }
        float a0, a1, c0, c1;
        unpack2(acc0, a0, a1);
        unpack2(acc1, c0, c1);
        const float part = (a0 + c0) + (a1 + c1);

        if (!own) {
            // ship partial to the row's owner FIRST; drains in background
            st_async_f32(r_ps[buf], part, r_mbar[buf]);

            // head partials for h(t-1) — hidden under the owners' wait
            if (worker && t > 0) {
                const ulonglong2* hh = reinterpret_cast<const ulonglong2*>(&hbuf[buf][hq << 4]);
                unsigned long long b0 = 0ull, b1 = 0ull;
#pragma unroll
                for (int i = 0; i < 4; i++) {
                    ulonglong2 hv = hh[i];
                    ffma2(b0, wh[2 * i],     hv.x);
                    ffma2(b1, wh[2 * i + 1], hv.y);
                }
                float p0, p1, p2, p3;
                unpack2(b0, p0, p1);
                unpack2(b1, p2, p3);
                float hpv = (p0 + p2) + (p1 + p3);
                hpv += __shfl_xor_sync(0xffffffffu, hpv, 1);
                hpv += __shfl_xor_sync(0xffffffffu, hpv, 2);
                if (hq == 0) hp_base[(size_t)(t - 1) * (CL * 24)] = hpv;
            }
        } else {
            mbar_wait(l_mbar[buf], ph[buf]);
            ph[buf] ^= 1;
            // own slot is permanently 0 -> unconditional 4-way sum
            float s = part + xv + bias
                    + ps_in[buf][0][lrow] + ps_in[buf][1][lrow]
                    + ps_in[buf][2][lrow] + ps_in[buf][3][lrow];
            float hn = tanh_approx(s);
            xv = xnext;
            hbuf[nb][lrow] = hn;                 // no g_enc store anymore
        }
        __syncthreads();
    }

    // final head partials for h(511) (in hbuf[0] after t=511 wrote nb=0)
    if (worker) {
        const ulonglong2* hh = reinterpret_cast<const ulonglong2*>(&hbuf[0][hq << 4]);
        unsigned long long b0 = 0ull, b1 = 0ull;
#pragma unroll
        for (int i = 0; i < 4; i++) {
            ulonglong2 hv = hh[i];
            ffma2(b0, wh[2 * i],     hv.x);
            ffma2(b1, wh[2 * i + 1], hv.y);
        }
        float p0, p1, p2, p3;
        unpack2(b0, p0, p1);
        unpack2(b1, p2, p3);
        float hpv = (p0 + p2) + (p1 + p3);
        hpv += __shfl_xor_sync(0xffffffffu, hpv, 1);
        hpv += __shfl_xor_sync(0xffffffffu, hpv, 2);
        if (hq == 0) hp_base[(size_t)(Tn - 1) * (CL * 24)] = hpv;
    }

    // keep smem/barriers alive until peers' in-flight st.asyncs complete
    asm volatile("barrier.cluster.arrive.aligned;" ::: "memory");
    asm volatile("barrier.cluster.wait.aligned;" ::: "memory");
}

// ---------------- kernel 3: reduce head partials (4 ranks) + bias ----------------
__global__ void __launch_bounds__(256) k_heads(const float* __restrict__ b_mean,
                                               const float* __restrict__ b_bd,
                                               float* __restrict__ out_mean) {
    const int idx = blockIdx.x * 256 + threadIdx.x;   // 0 .. Bn*Tn*24-1
    const int o  = idx % 24;
    const int bt = idx / 24;

    const float* p = g_hp + (size_t)bt * (CL * 24) + o;
    float s = (p[0] + p[24]) + (p[48] + p[72]);
    if (o < Dn) out_mean[(size_t)bt * Dn + o] = s + __ldg(b_mean + o);
    else        g_bd[(size_t)bt * (2 * Dn) + (o - Dn)] = s + __ldg(b_bd + (o - Dn));
}

// ---------------- kernel 4: tridiagonal writes only (zeros done in k_scan) ----------------
__global__ void __launch_bounds__(256) k_prec_diag(float* __restrict__ prec) {
    const int idx = blockIdx.x * 256 + threadIdx.x;   // 0 .. 65535 = (b*8+d)*512 + i
    const int i   = idx & 511;
    const int bd_ = idx >> 9;
    const int d   = bd_ & 7;
    const int b   = bd_ >> 3;

    const size_t row = ((size_t)b * Tn + i) * 16;
    float diag_i = g_bd[row + d];
    float off_i  = g_bd[row + 8 + d];
    float off_p  = 0.f;
    if (i > 0) off_p = g_bd[row - 16 + 8 + d];

    float mainv  = diag_i * diag_i + off_p * off_p + EPSf;
    float supd_r = diag_i * off_i;   // supd[i] (columns i/i+1)

    float* base = prec + ((size_t)bd_ * Tn + i) * Tn + i;   // [b,d,i,i]
    base[0] = mainv;
    if (i < Tn - 1) {
        base[1]  = supd_r;    // [i, i+1]
        base[Tn] = supd_r;    // [i+1, i]
    }
}

// ---------------- launch ----------------
extern "C" void kernel_launch(void* const* d_in, const int* in_sizes, int n_in,
                              void* d_out, int out_size) {
    const float* y      = (const float*)d_in[0];
    const float* W_ih   = (const float*)d_in[1];
    const float* W_hh   = (const float*)d_in[2];
    const float* b_ih   = (const float*)d_in[3];
    const float* b_hh   = (const float*)d_in[4];
    const float* W_mean = (const float*)d_in[5];
    const float* b_mean = (const float*)d_in[6];
    const float* W_bd   = (const float*)d_in[7];
    const float* b_bd   = (const float*)d_in[8];
    float* out = (float*)d_out;
    float* prec = out + Bn * Tn * Dn;

    k_xproj<<<dim3(Tn / 4, Bn), 256>>>(y, W_ih, b_ih);
    k_scan<<<GRID_SCAN, 256>>>(W_hh, b_hh, W_mean, W_bd, prec);  // scan + heads + zero-fill
    k_heads<<<(Bn * Tn * 24) / 256, 256>>>(b_mean, b_bd, out);
    k_prec_diag<<<(Bn * Dn * Tn) / 256, 256>>>(prec);
}